// round 4
// baseline (speedup 1.0000x reference)
#include <cuda_runtime.h>
#include <math.h>
#include <stdint.h>

constexpr int NN = 50000;   // nodes
constexpr int EE = 800000;  // edges
constexpr int NF = 512;     // input features
constexpr int NH = 96;      // hidden
constexpr int NC = 64;      // classes
constexpr int NL = 8;       // layers
constexpr float ALPHA = 0.1f;
constexpr int LDW = 100;    // padded leading dim (bank-conflict-free fragments)

constexpr int GBLK128 = (NN + 127) / 128;   // 391
constexpr int GBLK64  = (NN + 63) / 64;     // 782

// ---------------- scratch (device globals; no allocations allowed) ----------
__device__ __align__(16) float g_h [NN * NH];   // ping
__device__ __align__(16) float g_h2[NN * NH];   // pong
__device__ __align__(16) float g_x0[NN * NH];
__device__ int g_deg[NN];
__device__ int g_rowptr[NN + 1];
__device__ int g_cursor[NN];
__device__ int g_esrc[EE];
// pre-converted / pre-split weights (tf32-valid fp32 bit patterns), padded to LDW
__device__ __align__(16) float g_Wih[NF * LDW];
__device__ __align__(16) float g_Wil[NF * LDW];
__device__ __align__(16) float g_Wm [NL * NH * LDW];

// ---------------- tf32 helpers ----------------
__device__ __forceinline__ uint32_t f2tf(float f) {
    uint32_t u;
    asm("cvt.rna.tf32.f32 %0, %1;" : "=r"(u) : "f"(f));
    return u;
}

__device__ __forceinline__ void mma8(float* c, const uint32_t* a, const uint32_t* b) {
    asm volatile(
        "mma.sync.aligned.m16n8k8.row.col.f32.tf32.tf32.f32 "
        "{%0,%1,%2,%3}, {%4,%5,%6,%7}, {%8,%9}, {%0,%1,%2,%3};"
        : "+f"(c[0]), "+f"(c[1]), "+f"(c[2]), "+f"(c[3])
        : "r"(a[0]), "r"(a[1]), "r"(a[2]), "r"(a[3]), "r"(b[0]), "r"(b[1]));
}

// ---------------- weight prep (also zeroes g_deg) ----------------
__global__ void k_prep_in(const float* __restrict__ W) {
    int idx = blockIdx.x * blockDim.x + threadIdx.x;
    if (idx < NN) g_deg[idx] = 0;
    if (idx >= NF * LDW) return;
    int k = idx / LDW, n = idx % LDW;
    float hi = 0.f, lo = 0.f;
    if (n < NH) {
        float w = W[k * NH + n];
        uint32_t h = f2tf(w);
        hi = __uint_as_float(h);
        lo = __uint_as_float(f2tf(w - hi));
    }
    g_Wih[idx] = hi;
    g_Wil[idx] = lo;
}

__global__ void k_prep_wm(const float* __restrict__ convW) {
    int idx = blockIdx.x * blockDim.x + threadIdx.x;
    if (idx >= NL * NH * LDW) return;
    int l = idx / (NH * LDW);
    int r = (idx / LDW) % NH;
    int n = idx % LDW;
    float v = 0.f;
    if (n < NH) v = __uint_as_float(f2tf(convW[l * NH * NH + r * NH + n]));
    g_Wm[idx] = v;
}

// ---------------- CSR build ----------------
__global__ void k_hist(const int* __restrict__ dst) {
    int e4 = blockIdx.x * blockDim.x + threadIdx.x;
    if (e4 * 4 >= EE) return;
    int4 d = ((const int4*)dst)[e4];
    atomicAdd(&g_deg[d.x], 1);
    atomicAdd(&g_deg[d.y], 1);
    atomicAdd(&g_deg[d.z], 1);
    atomicAdd(&g_deg[d.w], 1);
}

__global__ void k_scan() {
    __shared__ int wsum[32];
    __shared__ int carry;
    int tid = threadIdx.x, lane = tid & 31, wid = tid >> 5;
    if (tid == 0) carry = 0;
    __syncthreads();
    for (int base = 0; base < NN; base += 1024) {
        int i = base + tid;
        int v = (i < NN) ? g_deg[i] : 0;
        int x = v;
        #pragma unroll
        for (int o = 1; o < 32; o <<= 1) {
            int t = __shfl_up_sync(0xffffffffu, x, o);
            if (lane >= o) x += t;
        }
        if (lane == 31) wsum[wid] = x;
        __syncthreads();
        if (wid == 0) {
            int w = wsum[lane];
            #pragma unroll
            for (int o = 1; o < 32; o <<= 1) {
                int t = __shfl_up_sync(0xffffffffu, w, o);
                if (lane >= o) w += t;
            }
            wsum[lane] = w;
        }
        __syncthreads();
        int wbase = wid ? wsum[wid - 1] : 0;
        int excl = carry + wbase + x - v;
        if (i < NN) { g_rowptr[i] = excl; g_cursor[i] = excl; }
        __syncthreads();
        if (tid == 0) carry += wsum[31];
        __syncthreads();
    }
    if (threadIdx.x == 0) g_rowptr[NN] = carry;
}

__global__ void k_fill(const int* __restrict__ src, const int* __restrict__ dst) {
    int e4 = blockIdx.x * blockDim.x + threadIdx.x;
    if (e4 * 4 >= EE) return;
    int4 d = ((const int4*)dst)[e4];
    int4 s = ((const int4*)src)[e4];
    int p0 = atomicAdd(&g_cursor[d.x], 1);
    int p1 = atomicAdd(&g_cursor[d.y], 1);
    int p2 = atomicAdd(&g_cursor[d.z], 1);
    int p3 = atomicAdd(&g_cursor[d.w], 1);
    g_esrc[p0] = s.x;
    g_esrc[p1] = s.y;
    g_esrc[p2] = s.z;
    g_esrc[p3] = s.w;
}

// ---------------- input GEMM (3xtf32): h = x0 = relu(x @ W_in + b_in) ------
__global__ void k_gemm_in(const float* __restrict__ x, const float* __restrict__ bias) {
    extern __shared__ float sm[];
    float* As = sm;                 // [128][36] raw fp32 activations
    float* Wh = sm + 128 * 36;      // [32][100]
    float* Wl = Wh + 32 * LDW;      // [32][100]
    int tid = threadIdx.x;
    int warp = tid >> 5, lane = tid & 31;
    int wm = warp >> 1, wn = warp & 1;
    int g = lane >> 2, q = lane & 3;
    int row0 = blockIdx.x * 128;

    float c[2][6][4];
    #pragma unroll
    for (int mt = 0; mt < 2; mt++)
        #pragma unroll
        for (int nt = 0; nt < 6; nt++)
            #pragma unroll
            for (int i = 0; i < 4; i++) c[mt][nt][i] = 0.f;

    for (int kb = 0; kb < NF / 32; kb++) {
        #pragma unroll
        for (int t = 0; t < 4; t++) {
            int idx = tid + t * 256;
            int r = idx >> 3, c4 = idx & 7;
            float4 v = make_float4(0.f, 0.f, 0.f, 0.f);
            if (row0 + r < NN)
                v = ((const float4*)x)[(size_t)(row0 + r) * (NF / 4) + kb * 8 + c4];
            *(float4*)&As[r * 36 + c4 * 4] = v;
        }
        #pragma unroll
        for (int t = 0; t < 4; t++) {
            int i = tid + t * 256;
            if (i < 800) {
                int r = i / 25, cc = i % 25;
                *(float4*)&Wh[r * LDW + cc * 4] = *(const float4*)&g_Wih[(kb * 32 + r) * LDW + cc * 4];
                *(float4*)&Wl[r * LDW + cc * 4] = *(const float4*)&g_Wil[(kb * 32 + r) * LDW + cc * 4];
            }
        }
        __syncthreads();

        #pragma unroll
        for (int ks = 0; ks < 4; ks++) {
            uint32_t ah[2][4], al[2][4], bh[6][2], bl[6][2];
            #pragma unroll
            for (int mt = 0; mt < 2; mt++) {
                int rbase = wm * 32 + mt * 16 + g;
                #pragma unroll
                for (int ii = 0; ii < 4; ii++) {
                    int rr = rbase + (ii & 1) * 8;
                    int kk = ks * 8 + q + (ii >> 1) * 4;
                    float a = As[rr * 36 + kk];
                    uint32_t hi = f2tf(a);
                    float lo = a - __uint_as_float(hi);
                    ah[mt][ii] = hi;
                    al[mt][ii] = f2tf(lo);
                }
            }
            #pragma unroll
            for (int nt = 0; nt < 6; nt++) {
                int ncol = wn * 48 + nt * 8 + g;
                int k0 = ks * 8 + q;
                bh[nt][0] = __float_as_uint(Wh[k0 * LDW + ncol]);
                bh[nt][1] = __float_as_uint(Wh[(k0 + 4) * LDW + ncol]);
                bl[nt][0] = __float_as_uint(Wl[k0 * LDW + ncol]);
                bl[nt][1] = __float_as_uint(Wl[(k0 + 4) * LDW + ncol]);
            }
            #pragma unroll
            for (int mt = 0; mt < 2; mt++)
                #pragma unroll
                for (int nt = 0; nt < 6; nt++) {
                    mma8(c[mt][nt], ah[mt], bh[nt]);
                    mma8(c[mt][nt], ah[mt], bl[nt]);
                    mma8(c[mt][nt], al[mt], bh[nt]);
                }
        }
        __syncthreads();
    }

    #pragma unroll
    for (int mt = 0; mt < 2; mt++) {
        #pragma unroll
        for (int nt = 0; nt < 6; nt++) {
            int col = wn * 48 + nt * 8 + 2 * q;
            float b0 = bias[col], b1 = bias[col + 1];
            int r0 = row0 + wm * 32 + mt * 16 + g;
            if (r0 < NN) {
                float2 v;
                v.x = fmaxf(c[mt][nt][0] + b0, 0.f);
                v.y = fmaxf(c[mt][nt][1] + b1, 0.f);
                *(float2*)&g_h [r0 * NH + col] = v;
                *(float2*)&g_x0[r0 * NH + col] = v;
            }
            int r1 = r0 + 8;
            if (r1 < NN) {
                float2 v;
                v.x = fmaxf(c[mt][nt][2] + b0, 0.f);
                v.y = fmaxf(c[mt][nt][3] + b1, 0.f);
                *(float2*)&g_h [r1 * NH + col] = v;
                *(float2*)&g_x0[r1 * NH + col] = v;
            }
        }
    }
}

// ---------------- fused layer: gather + hc blend + 1xtf32 GEMM + relu ------
// hc = 0.9*segsum(hin[src]->node) + 0.1*x0   (exact fp32, built in smem)
// hout = relu((1-beta)*hc + beta*(hc @ W))   (beta term via tf32 MMA)
__global__ void k_fused(int l, float beta,
                        const float* __restrict__ hin,
                        float* __restrict__ hout) {
    extern __shared__ float sm[];
    float* As = sm;                 // [128][100] gathered hc (fp32)
    float* Ws = sm + 128 * LDW;     // [96][100] tf32-valid W
    int tid = threadIdx.x;
    int warp = tid >> 5, lane = tid & 31;
    int wm = warp >> 1, wn = warp & 1;
    int g = lane >> 2, q = lane & 3;
    int row0 = blockIdx.x * 128;

    // load W: 96x100 -> 2400 float4
    const float* Wg = g_Wm + (size_t)l * NH * LDW;
    #pragma unroll
    for (int t = 0; t < 10; t++) {
        int i = tid + t * 256;
        if (i < 2400) {
            int r = i / 25, cc = i % 25;
            *(float4*)&Ws[r * LDW + cc * 4] = *(const float4*)&Wg[r * LDW + cc * 4];
        }
    }

    // gather phase: warp w handles rows [w*16, w*16+16); lanes 0..23 do float4
    const float4* __restrict__ h4 = (const float4*)hin;
    const float OA = 1.0f - ALPHA;
    if (lane < 24) {
        #pragma unroll 1
        for (int rr = 0; rr < 16; rr++) {
            int r = warp * 16 + rr;
            int node = row0 + r;
            float4 acc = make_float4(0.f, 0.f, 0.f, 0.f);
            if (node < NN) {
                int s = g_rowptr[node];
                int e = g_rowptr[node + 1];
                int i = s;
                for (; i + 8 <= e; i += 8) {
                    int s0 = g_esrc[i],     s1 = g_esrc[i + 1];
                    int s2 = g_esrc[i + 2], s3 = g_esrc[i + 3];
                    int s4 = g_esrc[i + 4], s5 = g_esrc[i + 5];
                    int s6 = g_esrc[i + 6], s7 = g_esrc[i + 7];
                    float4 v0 = h4[s0 * 24 + lane];
                    float4 v1 = h4[s1 * 24 + lane];
                    float4 v2 = h4[s2 * 24 + lane];
                    float4 v3 = h4[s3 * 24 + lane];
                    float4 v4 = h4[s4 * 24 + lane];
                    float4 v5 = h4[s5 * 24 + lane];
                    float4 v6 = h4[s6 * 24 + lane];
                    float4 v7 = h4[s7 * 24 + lane];
                    acc.x += ((v0.x + v1.x) + (v2.x + v3.x)) + ((v4.x + v5.x) + (v6.x + v7.x));
                    acc.y += ((v0.y + v1.y) + (v2.y + v3.y)) + ((v4.y + v5.y) + (v6.y + v7.y));
                    acc.z += ((v0.z + v1.z) + (v2.z + v3.z)) + ((v4.z + v5.z) + (v6.z + v7.z));
                    acc.w += ((v0.w + v1.w) + (v2.w + v3.w)) + ((v4.w + v5.w) + (v6.w + v7.w));
                }
                for (; i < e; i++) {
                    float4 v = h4[g_esrc[i] * 24 + lane];
                    acc.x += v.x; acc.y += v.y; acc.z += v.z; acc.w += v.w;
                }
                float4 x0v = ((const float4*)g_x0)[node * 24 + lane];
                acc.x = OA * acc.x + ALPHA * x0v.x;
                acc.y = OA * acc.y + ALPHA * x0v.y;
                acc.z = OA * acc.z + ALPHA * x0v.z;
                acc.w = OA * acc.w + ALPHA * x0v.w;
            }
            *(float4*)&As[r * LDW + lane * 4] = acc;
        }
    }
    __syncthreads();

    float c[2][6][4];
    #pragma unroll
    for (int mt = 0; mt < 2; mt++)
        #pragma unroll
        for (int nt = 0; nt < 6; nt++)
            #pragma unroll
            for (int i = 0; i < 4; i++) c[mt][nt][i] = 0.f;

    #pragma unroll
    for (int ks = 0; ks < NH / 8; ks++) {
        uint32_t a[2][4], b[6][2];
        #pragma unroll
        for (int mt = 0; mt < 2; mt++) {
            int rbase = wm * 32 + mt * 16 + g;
            #pragma unroll
            for (int ii = 0; ii < 4; ii++) {
                int rr = rbase + (ii & 1) * 8;
                int kk = ks * 8 + q + (ii >> 1) * 4;
                a[mt][ii] = f2tf(As[rr * LDW + kk]);
            }
        }
        #pragma unroll
        for (int nt = 0; nt < 6; nt++) {
            int ncol = wn * 48 + nt * 8 + g;
            int k0 = ks * 8 + q;
            b[nt][0] = __float_as_uint(Ws[k0 * LDW + ncol]);
            b[nt][1] = __float_as_uint(Ws[(k0 + 4) * LDW + ncol]);
        }
        #pragma unroll
        for (int mt = 0; mt < 2; mt++)
            #pragma unroll
            for (int nt = 0; nt < 6; nt++)
                mma8(c[mt][nt], a[mt], b[nt]);
    }

    float ob = 1.f - beta;
    #pragma unroll
    for (int mt = 0; mt < 2; mt++) {
        #pragma unroll
        for (int nt = 0; nt < 6; nt++) {
            int col = wn * 48 + nt * 8 + 2 * q;
            int rl0 = wm * 32 + mt * 16 + g;
            int r0 = row0 + rl0;
            if (r0 < NN) {
                float hc0 = As[rl0 * LDW + col];
                float hc1 = As[rl0 * LDW + col + 1];
                float2 v;
                v.x = fmaxf(ob * hc0 + beta * c[mt][nt][0], 0.f);
                v.y = fmaxf(ob * hc1 + beta * c[mt][nt][1], 0.f);
                *(float2*)&hout[r0 * NH + col] = v;
            }
            int rl1 = rl0 + 8;
            int r1 = r0 + 8;
            if (r1 < NN) {
                float hc0 = As[rl1 * LDW + col];
                float hc1 = As[rl1 * LDW + col + 1];
                float2 v;
                v.x = fmaxf(ob * hc0 + beta * c[mt][nt][2], 0.f);
                v.y = fmaxf(ob * hc1 + beta * c[mt][nt][3], 0.f);
                *(float2*)&hout[r1 * NH + col] = v;
            }
        }
    }
}

// ---------------- output GEMM + log-softmax (fp32 FFMA) --------------------
__global__ void k_out(const float* __restrict__ W,
                      const float* __restrict__ b,
                      float* __restrict__ out) {
    extern __shared__ float sm[];
    float* As = sm;               // 64*96
    float* Ws = sm + 64 * NH;     // 96*64
    int tid = threadIdx.x;
    int rg = tid >> 4, cg = tid & 15;
    int row0 = blockIdx.x * 64;

    #pragma unroll
    for (int t = 0; t < 6; t++) {
        int idx = tid + t * 256;
        ((float4*)Ws)[idx] = ((const float4*)W)[idx];
    }
    #pragma unroll
    for (int t = 0; t < 6; t++) {
        int idx = tid + t * 256;
        int r = idx / 24, c4 = idx % 24;
        float4 v = make_float4(0.f, 0.f, 0.f, 0.f);
        int row = row0 + r;
        if (row < NN) v = ((const float4*)g_h)[row * 24 + c4];
        ((float4*)As)[idx] = v;
    }
    __syncthreads();

    float acc[4][4];
    #pragma unroll
    for (int i = 0; i < 4; i++)
        #pragma unroll
        for (int j = 0; j < 4; j++) acc[i][j] = 0.f;

    #pragma unroll 4
    for (int k = 0; k < NH; k++) {
        float a[4], bb[4];
        #pragma unroll
        for (int i = 0; i < 4; i++) a[i] = As[(rg * 4 + i) * NH + k];
        #pragma unroll
        for (int j = 0; j < 4; j++) bb[j] = Ws[k * NC + cg * 4 + j];
        #pragma unroll
        for (int i = 0; i < 4; i++)
            #pragma unroll
            for (int j = 0; j < 4; j++) acc[i][j] = fmaf(a[i], bb[j], acc[i][j]);
    }

    #pragma unroll
    for (int i = 0; i < 4; i++)
        #pragma unroll
        for (int j = 0; j < 4; j++) acc[i][j] += b[cg * 4 + j];

    #pragma unroll
    for (int i = 0; i < 4; i++) {
        float m = fmaxf(fmaxf(acc[i][0], acc[i][1]), fmaxf(acc[i][2], acc[i][3]));
        #pragma unroll
        for (int off = 8; off >= 1; off >>= 1)
            m = fmaxf(m, __shfl_xor_sync(0xffffffffu, m, off, 16));
        float s = __expf(acc[i][0] - m) + __expf(acc[i][1] - m)
                + __expf(acc[i][2] - m) + __expf(acc[i][3] - m);
        #pragma unroll
        for (int off = 8; off >= 1; off >>= 1)
            s += __shfl_xor_sync(0xffffffffu, s, off, 16);
        float lse = m + logf(s);
        int row = row0 + rg * 4 + i;
        if (row < NN) {
            #pragma unroll
            for (int j = 0; j < 4; j++)
                out[row * NC + cg * 4 + j] = acc[i][j] - lse;
        }
    }
}

// ---------------- launch ----------------------------------------------------
extern "C" void kernel_launch(void* const* d_in, const int* in_sizes, int n_in,
                              void* d_out, int out_size) {
    const float* x      = (const float*)d_in[0];
    const int*   ei     = (const int*)  d_in[1];
    const float* W_in   = (const float*)d_in[2];
    const float* b_in   = (const float*)d_in[3];
    const float* conv_W = (const float*)d_in[4];
    const float* W_out  = (const float*)d_in[5];
    const float* b_out  = (const float*)d_in[6];
    float* out = (float*)d_out;

    const int* src = ei;        // edge_index[0]
    const int* dst = ei + EE;   // edge_index[1]

    const int IN_SMEM    = (128 * 36 + 2 * 32 * LDW) * 4;   // 44032
    const int LAYER_SMEM = (128 * LDW + NH * LDW) * 4;      // 89600
    const int OUT_SMEM   = (64 * NH + NH * NC) * 4;         // 49152
    cudaFuncSetAttribute(k_gemm_in, cudaFuncAttributeMaxDynamicSharedMemorySize, IN_SMEM);
    cudaFuncSetAttribute(k_fused,   cudaFuncAttributeMaxDynamicSharedMemorySize, LAYER_SMEM);
    cudaFuncSetAttribute(k_out,     cudaFuncAttributeMaxDynamicSharedMemorySize, OUT_SMEM);

    // weight prep (tf32 rounding / splitting); k_prep_in also zeroes g_deg
    k_prep_in<<<(NF * LDW + 255) / 256, 256>>>(W_in);
    k_prep_wm<<<(NL * NH * LDW + 255) / 256, 256>>>(conv_W);

    // CSR build (4 edges per thread)
    k_hist<<<(EE / 4 + 255) / 256, 256>>>(dst);
    k_scan<<<1, 1024>>>();
    k_fill<<<(EE / 4 + 255) / 256, 256>>>(src, dst);

    // input projection -> g_h (+ g_x0)
    k_gemm_in<<<GBLK128, 256, IN_SMEM>>>(x, b_in);

    // 8 fused GCNII layers, ping-pong g_h <-> g_h2
    float* bufA; float* bufB;
    cudaGetSymbolAddress((void**)&bufA, g_h);
    cudaGetSymbolAddress((void**)&bufB, g_h2);
    for (int l = 0; l < NL; l++) {
        float beta = (float)log(0.5 / (double)(l + 1) + 1.0);
        const float* hin = (l & 1) ? bufB : bufA;
        float* hout      = (l & 1) ? bufA : bufB;
        k_fused<<<GBLK128, 256, LAYER_SMEM>>>(l, beta, hin, hout);
    }
    // NL even -> final h is in g_h (bufA)

    // output + log-softmax
    k_out<<<GBLK64, 256, OUT_SMEM>>>(W_out, b_out, out);
}

// round 6
// speedup vs baseline: 1.5538x; 1.5538x over previous
#include <cuda_runtime.h>
#include <math.h>
#include <stdint.h>

constexpr int NN = 50000;   // nodes
constexpr int EE = 800000;  // edges
constexpr int NF = 512;     // input features
constexpr int NH = 96;      // hidden
constexpr int NC = 64;      // classes
constexpr int NL = 8;       // layers
constexpr float ALPHA = 0.1f;
constexpr int LDW = 100;    // padded leading dim (bank-conflict-free fragments)

constexpr int GBLK128 = (NN + 127) / 128;   // 391
constexpr int GBLK64  = (NN + 63) / 64;     // 782
constexpr int SCAN_B  = (NN + 1023) / 1024; // 49 scan blocks

// ---------------- scratch (device globals; no allocations allowed) ----------
__device__ __align__(16) float g_h [NN * NH];
__device__ __align__(16) float g_x0[NN * NH];
__device__ __align__(16) float g_hc[NN * NH];
__device__ int g_deg[NN];
__device__ int g_rowptr[NN + 1];
__device__ int g_cursor[NN];
__device__ int g_esrc[EE];
__device__ int g_bsum[SCAN_B];
__device__ int g_boff[SCAN_B];
// pre-converted / pre-split weights (tf32-valid fp32 bit patterns), padded to LDW
__device__ __align__(16) float g_Wih[NF * LDW];
__device__ __align__(16) float g_Wil[NF * LDW];
__device__ __align__(16) float g_Wm [NL * NH * LDW];

// ---------------- tf32 helpers ----------------
__device__ __forceinline__ uint32_t f2tf(float f) {
    uint32_t u;
    asm("cvt.rna.tf32.f32 %0, %1;" : "=r"(u) : "f"(f));
    return u;
}

__device__ __forceinline__ void mma8(float* c, const uint32_t* a, const uint32_t* b) {
    asm volatile(
        "mma.sync.aligned.m16n8k8.row.col.f32.tf32.tf32.f32 "
        "{%0,%1,%2,%3}, {%4,%5,%6,%7}, {%8,%9}, {%0,%1,%2,%3};"
        : "+f"(c[0]), "+f"(c[1]), "+f"(c[2]), "+f"(c[3])
        : "r"(a[0]), "r"(a[1]), "r"(a[2]), "r"(a[3]), "r"(b[0]), "r"(b[1]));
}

// ---------------- weight prep (also zeroes g_deg) ----------------
__global__ void k_prep_in(const float* __restrict__ W) {
    int idx = blockIdx.x * blockDim.x + threadIdx.x;
    if (idx < NN) g_deg[idx] = 0;
    if (idx >= NF * LDW) return;
    int k = idx / LDW, n = idx % LDW;
    float hi = 0.f, lo = 0.f;
    if (n < NH) {
        float w = W[k * NH + n];
        uint32_t h = f2tf(w);
        hi = __uint_as_float(h);
        lo = __uint_as_float(f2tf(w - hi));
    }
    g_Wih[idx] = hi;
    g_Wil[idx] = lo;
}

__global__ void k_prep_wm(const float* __restrict__ convW) {
    int idx = blockIdx.x * blockDim.x + threadIdx.x;
    if (idx >= NL * NH * LDW) return;
    int l = idx / (NH * LDW);
    int r = (idx / LDW) % NH;
    int n = idx % LDW;
    float v = 0.f;
    if (n < NH) v = __uint_as_float(f2tf(convW[l * NH * NH + r * NH + n]));
    g_Wm[idx] = v;
}

// ---------------- CSR build ----------------
__global__ void k_hist(const int* __restrict__ dst) {
    int e4 = blockIdx.x * blockDim.x + threadIdx.x;
    if (e4 * 4 >= EE) return;
    int4 d = ((const int4*)dst)[e4];
    atomicAdd(&g_deg[d.x], 1);
    atomicAdd(&g_deg[d.y], 1);
    atomicAdd(&g_deg[d.z], 1);
    atomicAdd(&g_deg[d.w], 1);
}

// phase 1: per-block exclusive scan of 1024 elements + block total
__global__ void k_scan1() {
    __shared__ int wsum[32];
    int tid = threadIdx.x, lane = tid & 31, wid = tid >> 5;
    int i = blockIdx.x * 1024 + tid;
    int v = (i < NN) ? g_deg[i] : 0;
    int x = v;
    #pragma unroll
    for (int o = 1; o < 32; o <<= 1) {
        int t = __shfl_up_sync(0xffffffffu, x, o);
        if (lane >= o) x += t;
    }
    if (lane == 31) wsum[wid] = x;
    __syncthreads();
    if (wid == 0) {
        int w = wsum[lane];
        #pragma unroll
        for (int o = 1; o < 32; o <<= 1) {
            int t = __shfl_up_sync(0xffffffffu, w, o);
            if (lane >= o) w += t;
        }
        wsum[lane] = w;
    }
    __syncthreads();
    int wbase = wid ? wsum[wid - 1] : 0;
    if (i < NN) g_rowptr[i] = wbase + x - v;   // block-local exclusive
    if (tid == 1023) g_bsum[blockIdx.x] = wbase + x;
}

// phase 2: 64-thread exclusive scan of the 49 block totals (flat indexing)
__global__ void k_scan2() {
    __shared__ int w0;
    int tid = threadIdx.x;            // 0..63
    int lane = tid & 31, w = tid >> 5;
    int v = (tid < SCAN_B) ? g_bsum[tid] : 0;
    int x = v;
    #pragma unroll
    for (int o = 1; o < 32; o <<= 1) {
        int t = __shfl_up_sync(0xffffffffu, x, o);
        if (lane >= o) x += t;
    }
    if (w == 0 && lane == 31) w0 = x;   // total of elements 0..31
    __syncthreads();
    int base = w ? w0 : 0;
    if (tid < SCAN_B) g_boff[tid] = base + x - v;
    if (tid == SCAN_B - 1) g_rowptr[NN] = base + x;
}

// phase 3: add block offsets; produce final rowptr + cursor
__global__ void k_scan3() {
    int i = blockIdx.x * 1024 + threadIdx.x;
    if (i < NN) {
        int r = g_rowptr[i] + g_boff[blockIdx.x];
        g_rowptr[i] = r;
        g_cursor[i] = r;
    }
}

__global__ void k_fill(const int* __restrict__ src, const int* __restrict__ dst) {
    int e4 = blockIdx.x * blockDim.x + threadIdx.x;
    if (e4 * 4 >= EE) return;
    int4 d = ((const int4*)dst)[e4];
    int4 s = ((const int4*)src)[e4];
    int p0 = atomicAdd(&g_cursor[d.x], 1);
    int p1 = atomicAdd(&g_cursor[d.y], 1);
    int p2 = atomicAdd(&g_cursor[d.z], 1);
    int p3 = atomicAdd(&g_cursor[d.w], 1);
    g_esrc[p0] = s.x;
    g_esrc[p1] = s.y;
    g_esrc[p2] = s.z;
    g_esrc[p3] = s.w;
}

// ---------------- input GEMM (3xtf32): h = x0 = relu(x @ W_in + b_in) ------
__global__ void k_gemm_in(const float* __restrict__ x, const float* __restrict__ bias) {
    extern __shared__ float sm[];
    float* As = sm;                 // [128][36] raw fp32 activations
    float* Wh = sm + 128 * 36;      // [32][100]
    float* Wl = Wh + 32 * LDW;      // [32][100]
    int tid = threadIdx.x;
    int warp = tid >> 5, lane = tid & 31;
    int wm = warp >> 1, wn = warp & 1;
    int g = lane >> 2, q = lane & 3;
    int row0 = blockIdx.x * 128;

    float c[2][6][4];
    #pragma unroll
    for (int mt = 0; mt < 2; mt++)
        #pragma unroll
        for (int nt = 0; nt < 6; nt++)
            #pragma unroll
            for (int i = 0; i < 4; i++) c[mt][nt][i] = 0.f;

    for (int kb = 0; kb < NF / 32; kb++) {
        #pragma unroll
        for (int t = 0; t < 4; t++) {
            int idx = tid + t * 256;
            int r = idx >> 3, c4 = idx & 7;
            float4 v = make_float4(0.f, 0.f, 0.f, 0.f);
            if (row0 + r < NN)
                v = ((const float4*)x)[(size_t)(row0 + r) * (NF / 4) + kb * 8 + c4];
            *(float4*)&As[r * 36 + c4 * 4] = v;
        }
        #pragma unroll
        for (int t = 0; t < 4; t++) {
            int i = tid + t * 256;
            if (i < 800) {
                int r = i / 25, cc = i % 25;
                *(float4*)&Wh[r * LDW + cc * 4] = *(const float4*)&g_Wih[(kb * 32 + r) * LDW + cc * 4];
                *(float4*)&Wl[r * LDW + cc * 4] = *(const float4*)&g_Wil[(kb * 32 + r) * LDW + cc * 4];
            }
        }
        __syncthreads();

        #pragma unroll
        for (int ks = 0; ks < 4; ks++) {
            uint32_t ah[2][4], al[2][4], bh[6][2], bl[6][2];
            #pragma unroll
            for (int mt = 0; mt < 2; mt++) {
                int rbase = wm * 32 + mt * 16 + g;
                #pragma unroll
                for (int ii = 0; ii < 4; ii++) {
                    int rr = rbase + (ii & 1) * 8;
                    int kk = ks * 8 + q + (ii >> 1) * 4;
                    float a = As[rr * 36 + kk];
                    uint32_t hi = f2tf(a);
                    float lo = a - __uint_as_float(hi);
                    ah[mt][ii] = hi;
                    al[mt][ii] = f2tf(lo);
                }
            }
            #pragma unroll
            for (int nt = 0; nt < 6; nt++) {
                int ncol = wn * 48 + nt * 8 + g;
                int k0 = ks * 8 + q;
                bh[nt][0] = __float_as_uint(Wh[k0 * LDW + ncol]);
                bh[nt][1] = __float_as_uint(Wh[(k0 + 4) * LDW + ncol]);
                bl[nt][0] = __float_as_uint(Wl[k0 * LDW + ncol]);
                bl[nt][1] = __float_as_uint(Wl[(k0 + 4) * LDW + ncol]);
            }
            #pragma unroll
            for (int mt = 0; mt < 2; mt++)
                #pragma unroll
                for (int nt = 0; nt < 6; nt++) {
                    mma8(c[mt][nt], ah[mt], bh[nt]);
                    mma8(c[mt][nt], ah[mt], bl[nt]);
                    mma8(c[mt][nt], al[mt], bh[nt]);
                }
        }
        __syncthreads();
    }

    #pragma unroll
    for (int mt = 0; mt < 2; mt++) {
        #pragma unroll
        for (int nt = 0; nt < 6; nt++) {
            int col = wn * 48 + nt * 8 + 2 * q;
            float b0 = bias[col], b1 = bias[col + 1];
            int r0 = row0 + wm * 32 + mt * 16 + g;
            if (r0 < NN) {
                float2 v;
                v.x = fmaxf(c[mt][nt][0] + b0, 0.f);
                v.y = fmaxf(c[mt][nt][1] + b1, 0.f);
                *(float2*)&g_h [r0 * NH + col] = v;
                *(float2*)&g_x0[r0 * NH + col] = v;
            }
            int r1 = r0 + 8;
            if (r1 < NN) {
                float2 v;
                v.x = fmaxf(c[mt][nt][2] + b0, 0.f);
                v.y = fmaxf(c[mt][nt][3] + b1, 0.f);
                *(float2*)&g_h [r1 * NH + col] = v;
                *(float2*)&g_x0[r1 * NH + col] = v;
            }
        }
    }
}

// ---------------- aggregation: hc = 0.9*segsum(h[src]->dst) + 0.1*x0 -------
// one warp per node; lanes 0..23 each own a float4 (4 features); 8-edge unroll
__global__ void k_agg() {
    int gw = (blockIdx.x * 256 + threadIdx.x) >> 5;
    int lane = threadIdx.x & 31;
    if (gw >= NN) return;
    int s = g_rowptr[gw];
    int e = g_rowptr[gw + 1];
    if (lane >= 24) return;
    const float4* __restrict__ h4 = (const float4*)g_h;
    float4 acc = make_float4(0.f, 0.f, 0.f, 0.f);
    int i = s;
    for (; i + 8 <= e; i += 8) {
        int s0 = g_esrc[i],     s1 = g_esrc[i + 1];
        int s2 = g_esrc[i + 2], s3 = g_esrc[i + 3];
        int s4 = g_esrc[i + 4], s5 = g_esrc[i + 5];
        int s6 = g_esrc[i + 6], s7 = g_esrc[i + 7];
        float4 v0 = h4[s0 * 24 + lane];
        float4 v1 = h4[s1 * 24 + lane];
        float4 v2 = h4[s2 * 24 + lane];
        float4 v3 = h4[s3 * 24 + lane];
        float4 v4 = h4[s4 * 24 + lane];
        float4 v5 = h4[s5 * 24 + lane];
        float4 v6 = h4[s6 * 24 + lane];
        float4 v7 = h4[s7 * 24 + lane];
        acc.x += ((v0.x + v1.x) + (v2.x + v3.x)) + ((v4.x + v5.x) + (v6.x + v7.x));
        acc.y += ((v0.y + v1.y) + (v2.y + v3.y)) + ((v4.y + v5.y) + (v6.y + v7.y));
        acc.z += ((v0.z + v1.z) + (v2.z + v3.z)) + ((v4.z + v5.z) + (v6.z + v7.z));
        acc.w += ((v0.w + v1.w) + (v2.w + v3.w)) + ((v4.w + v5.w) + (v6.w + v7.w));
    }
    for (; i < e; i++) {
        float4 v = h4[g_esrc[i] * 24 + lane];
        acc.x += v.x; acc.y += v.y; acc.z += v.z; acc.w += v.w;
    }
    float4 x0v = ((const float4*)g_x0)[gw * 24 + lane];
    float4 hc;
    const float OA = 1.0f - ALPHA;
    hc.x = OA * acc.x + ALPHA * x0v.x;
    hc.y = OA * acc.y + ALPHA * x0v.y;
    hc.z = OA * acc.z + ALPHA * x0v.z;
    hc.w = OA * acc.w + ALPHA * x0v.w;
    ((float4*)g_hc)[gw * 24 + lane] = hc;
}

// ---------------- layer GEMM (1xtf32 on beta term) -------------------------
// h = relu((1-b)*hc + b*(hc @ W)); residual term stays exact fp32 (from smem)
__global__ void k_layer(int l, float beta) {
    extern __shared__ float sm[];
    float* As = sm;                 // [128][100] raw fp32 hc
    float* Ws = sm + 128 * LDW;     // [96][100] tf32-valid W
    int tid = threadIdx.x;
    int warp = tid >> 5, lane = tid & 31;
    int wm = warp >> 1, wn = warp & 1;
    int g = lane >> 2, q = lane & 3;
    int row0 = blockIdx.x * 128;

    #pragma unroll
    for (int t = 0; t < 12; t++) {
        int i = tid + t * 256;
        int r = i / 24, cc = i % 24;
        float4 v = make_float4(0.f, 0.f, 0.f, 0.f);
        if (row0 + r < NN) v = ((const float4*)g_hc)[(row0 + r) * 24 + cc];
        *(float4*)&As[r * LDW + cc * 4] = v;
    }
    const float* Wg = g_Wm + (size_t)l * NH * LDW;
    #pragma unroll
    for (int t = 0; t < 10; t++) {
        int i = tid + t * 256;
        if (i < 2400) {
            int r = i / 25, cc = i % 25;
            *(float4*)&Ws[r * LDW + cc * 4] = *(const float4*)&Wg[r * LDW + cc * 4];
        }
    }
    __syncthreads();

    float c[2][6][4];
    #pragma unroll
    for (int mt = 0; mt < 2; mt++)
        #pragma unroll
        for (int nt = 0; nt < 6; nt++)
            #pragma unroll
            for (int i = 0; i < 4; i++) c[mt][nt][i] = 0.f;

    #pragma unroll
    for (int ks = 0; ks < NH / 8; ks++) {
        uint32_t a[2][4], b[6][2];
        #pragma unroll
        for (int mt = 0; mt < 2; mt++) {
            int rbase = wm * 32 + mt * 16 + g;
            #pragma unroll
            for (int ii = 0; ii < 4; ii++) {
                int rr = rbase + (ii & 1) * 8;
                int kk = ks * 8 + q + (ii >> 1) * 4;
                a[mt][ii] = f2tf(As[rr * LDW + kk]);
            }
        }
        #pragma unroll
        for (int nt = 0; nt < 6; nt++) {
            int ncol = wn * 48 + nt * 8 + g;
            int k0 = ks * 8 + q;
            b[nt][0] = __float_as_uint(Ws[k0 * LDW + ncol]);
            b[nt][1] = __float_as_uint(Ws[(k0 + 4) * LDW + ncol]);
        }
        #pragma unroll
        for (int mt = 0; mt < 2; mt++)
            #pragma unroll
            for (int nt = 0; nt < 6; nt++)
                mma8(c[mt][nt], a[mt], b[nt]);
    }

    float ob = 1.f - beta;
    #pragma unroll
    for (int mt = 0; mt < 2; mt++) {
        #pragma unroll
        for (int nt = 0; nt < 6; nt++) {
            int col = wn * 48 + nt * 8 + 2 * q;
            int rl0 = wm * 32 + mt * 16 + g;
            int r0 = row0 + rl0;
            if (r0 < NN) {
                float hc0 = As[rl0 * LDW + col];
                float hc1 = As[rl0 * LDW + col + 1];
                float2 v;
                v.x = fmaxf(ob * hc0 + beta * c[mt][nt][0], 0.f);
                v.y = fmaxf(ob * hc1 + beta * c[mt][nt][1], 0.f);
                *(float2*)&g_h[r0 * NH + col] = v;
            }
            int rl1 = rl0 + 8;
            int r1 = r0 + 8;
            if (r1 < NN) {
                float hc0 = As[rl1 * LDW + col];
                float hc1 = As[rl1 * LDW + col + 1];
                float2 v;
                v.x = fmaxf(ob * hc0 + beta * c[mt][nt][2], 0.f);
                v.y = fmaxf(ob * hc1 + beta * c[mt][nt][3], 0.f);
                *(float2*)&g_h[r1 * NH + col] = v;
            }
        }
    }
}

// ---------------- output GEMM + log-softmax (fp32 FFMA) --------------------
__global__ void k_out(const float* __restrict__ W,
                      const float* __restrict__ b,
                      float* __restrict__ out) {
    extern __shared__ float sm[];
    float* As = sm;               // 64*96
    float* Ws = sm + 64 * NH;     // 96*64
    int tid = threadIdx.x;
    int rg = tid >> 4, cg = tid & 15;
    int row0 = blockIdx.x * 64;

    #pragma unroll
    for (int t = 0; t < 6; t++) {
        int idx = tid + t * 256;
        ((float4*)Ws)[idx] = ((const float4*)W)[idx];
    }
    #pragma unroll
    for (int t = 0; t < 6; t++) {
        int idx = tid + t * 256;
        int r = idx / 24, c4 = idx % 24;
        float4 v = make_float4(0.f, 0.f, 0.f, 0.f);
        int row = row0 + r;
        if (row < NN) v = ((const float4*)g_h)[row * 24 + c4];
        ((float4*)As)[idx] = v;
    }
    __syncthreads();

    float acc[4][4];
    #pragma unroll
    for (int i = 0; i < 4; i++)
        #pragma unroll
        for (int j = 0; j < 4; j++) acc[i][j] = 0.f;

    #pragma unroll 4
    for (int k = 0; k < NH; k++) {
        float a[4], bb[4];
        #pragma unroll
        for (int i = 0; i < 4; i++) a[i] = As[(rg * 4 + i) * NH + k];
        #pragma unroll
        for (int j = 0; j < 4; j++) bb[j] = Ws[k * NC + cg * 4 + j];
        #pragma unroll
        for (int i = 0; i < 4; i++)
            #pragma unroll
            for (int j = 0; j < 4; j++) acc[i][j] = fmaf(a[i], bb[j], acc[i][j]);
    }

    #pragma unroll
    for (int i = 0; i < 4; i++)
        #pragma unroll
        for (int j = 0; j < 4; j++) acc[i][j] += b[cg * 4 + j];

    #pragma unroll
    for (int i = 0; i < 4; i++) {
        float m = fmaxf(fmaxf(acc[i][0], acc[i][1]), fmaxf(acc[i][2], acc[i][3]));
        #pragma unroll
        for (int off = 8; off >= 1; off >>= 1)
            m = fmaxf(m, __shfl_xor_sync(0xffffffffu, m, off, 16));
        float s = __expf(acc[i][0] - m) + __expf(acc[i][1] - m)
                + __expf(acc[i][2] - m) + __expf(acc[i][3] - m);
        #pragma unroll
        for (int off = 8; off >= 1; off >>= 1)
            s += __shfl_xor_sync(0xffffffffu, s, off, 16);
        float lse = m + logf(s);
        int row = row0 + rg * 4 + i;
        if (row < NN) {
            #pragma unroll
            for (int j = 0; j < 4; j++)
                out[row * NC + cg * 4 + j] = acc[i][j] - lse;
        }
    }
}

// ---------------- launch ----------------------------------------------------
extern "C" void kernel_launch(void* const* d_in, const int* in_sizes, int n_in,
                              void* d_out, int out_size) {
    const float* x      = (const float*)d_in[0];
    const int*   ei     = (const int*)  d_in[1];
    const float* W_in   = (const float*)d_in[2];
    const float* b_in   = (const float*)d_in[3];
    const float* conv_W = (const float*)d_in[4];
    const float* W_out  = (const float*)d_in[5];
    const float* b_out  = (const float*)d_in[6];
    float* out = (float*)d_out;

    const int* src = ei;        // edge_index[0]
    const int* dst = ei + EE;   // edge_index[1]

    const int IN_SMEM    = (128 * 36 + 2 * 32 * LDW) * 4;   // 44032
    const int LAYER_SMEM = (128 * LDW + NH * LDW) * 4;      // 89600
    const int OUT_SMEM   = (64 * NH + NH * NC) * 4;         // 49152
    cudaFuncSetAttribute(k_gemm_in, cudaFuncAttributeMaxDynamicSharedMemorySize, IN_SMEM);
    cudaFuncSetAttribute(k_layer,   cudaFuncAttributeMaxDynamicSharedMemorySize, LAYER_SMEM);
    cudaFuncSetAttribute(k_out,     cudaFuncAttributeMaxDynamicSharedMemorySize, OUT_SMEM);

    // weight prep (tf32 rounding / splitting); k_prep_in also zeroes g_deg
    k_prep_in<<<(NF * LDW + 255) / 256, 256>>>(W_in);
    k_prep_wm<<<(NL * NH * LDW + 255) / 256, 256>>>(conv_W);

    // CSR build (multi-block scan)
    k_hist<<<(EE / 4 + 255) / 256, 256>>>(dst);
    k_scan1<<<SCAN_B, 1024>>>();
    k_scan2<<<1, 64>>>();
    k_scan3<<<SCAN_B, 1024>>>();
    k_fill<<<(EE / 4 + 255) / 256, 256>>>(src, dst);

    // input projection -> g_h (+ g_x0)
    k_gemm_in<<<GBLK128, 256, IN_SMEM>>>(x, b_in);

    // 8 GCNII layers (split agg + layer GEMM)
    for (int l = 0; l < NL; l++) {
        float beta = (float)log(0.5 / (double)(l + 1) + 1.0);
        k_agg<<<NN / 8, 256>>>();
        k_layer<<<GBLK128, 256, LAYER_SMEM>>>(l, beta);
    }

    // output + log-softmax
    k_out<<<GBLK64, 256, OUT_SMEM>>>(W_out, b_out, out);
}

// round 7
// speedup vs baseline: 1.7712x; 1.1399x over previous
#include <cuda_runtime.h>
#include <math.h>
#include <stdint.h>

constexpr int NN = 50000;   // nodes
constexpr int EE = 800000;  // edges
constexpr int NF = 512;     // input features
constexpr int NH = 96;      // hidden
constexpr int NC = 64;      // classes
constexpr int NL = 8;       // layers
constexpr float ALPHA = 0.1f;
constexpr int LDW = 100;    // padded leading dim (bank-conflict-free fragments)
constexpr int LDO = 72;     // padded leading dim for W_out (bank-conflict-free)
constexpr int LDL = 68;     // padded leading dim for logits tile

constexpr int GBLK128 = (NN + 127) / 128;   // 391
constexpr int SCAN_B  = (NN + 1023) / 1024; // 49 scan blocks
constexpr int PERS    = 296;                // persistent CTAs for k_layer

// ---------------- scratch (device globals; no allocations allowed) ----------
__device__ __align__(16) float g_h [NN * NH];
__device__ __align__(16) float g_x0[NN * NH];
__device__ __align__(16) float g_hc[NN * NH];
__device__ int g_deg[NN];
__device__ int g_rowptr[NN + 1];
__device__ int g_cursor[NN];
__device__ int g_esrc[EE];
__device__ int g_bsum[SCAN_B];
__device__ int g_boff[SCAN_B];
// pre-converted weights (tf32-valid fp32 bit patterns), padded
__device__ __align__(16) float g_Wih[NF * LDW];
__device__ __align__(16) float g_Wm [NL * NH * LDW];
__device__ __align__(16) float g_Wo [NH * LDO];

// ---------------- tf32 helpers ----------------
__device__ __forceinline__ uint32_t f2tf(float f) {
    uint32_t u;
    asm("cvt.rna.tf32.f32 %0, %1;" : "=r"(u) : "f"(f));
    return u;
}

__device__ __forceinline__ void mma8(float* c, const uint32_t* a, const uint32_t* b) {
    asm volatile(
        "mma.sync.aligned.m16n8k8.row.col.f32.tf32.tf32.f32 "
        "{%0,%1,%2,%3}, {%4,%5,%6,%7}, {%8,%9}, {%0,%1,%2,%3};"
        : "+f"(c[0]), "+f"(c[1]), "+f"(c[2]), "+f"(c[3])
        : "r"(a[0]), "r"(a[1]), "r"(a[2]), "r"(a[3]), "r"(b[0]), "r"(b[1]));
}

// ---------------- weight prep (also zeroes g_deg) ----------------
__global__ void k_prep_in(const float* __restrict__ W) {
    int idx = blockIdx.x * blockDim.x + threadIdx.x;
    if (idx < NN) g_deg[idx] = 0;
    if (idx >= NF * LDW) return;
    int k = idx / LDW, n = idx % LDW;
    float hi = 0.f;
    if (n < NH) hi = __uint_as_float(f2tf(W[k * NH + n]));
    g_Wih[idx] = hi;
}

__global__ void k_prep_wm(const float* __restrict__ convW) {
    int idx = blockIdx.x * blockDim.x + threadIdx.x;
    if (idx >= NL * NH * LDW) return;
    int l = idx / (NH * LDW);
    int r = (idx / LDW) % NH;
    int n = idx % LDW;
    float v = 0.f;
    if (n < NH) v = __uint_as_float(f2tf(convW[l * NH * NH + r * NH + n]));
    g_Wm[idx] = v;
}

__global__ void k_prep_out(const float* __restrict__ Wout) {
    int idx = blockIdx.x * blockDim.x + threadIdx.x;
    if (idx >= NH * LDO) return;
    int r = idx / LDO, n = idx % LDO;
    float v = 0.f;
    if (n < NC) v = __uint_as_float(f2tf(Wout[r * NC + n]));
    g_Wo[idx] = v;
}

// ---------------- CSR build ----------------
__global__ void k_hist(const int* __restrict__ dst) {
    int e4 = blockIdx.x * blockDim.x + threadIdx.x;
    if (e4 * 4 >= EE) return;
    int4 d = ((const int4*)dst)[e4];
    atomicAdd(&g_deg[d.x], 1);
    atomicAdd(&g_deg[d.y], 1);
    atomicAdd(&g_deg[d.z], 1);
    atomicAdd(&g_deg[d.w], 1);
}

__global__ void k_scan1() {
    __shared__ int wsum[32];
    int tid = threadIdx.x, lane = tid & 31, wid = tid >> 5;
    int i = blockIdx.x * 1024 + tid;
    int v = (i < NN) ? g_deg[i] : 0;
    int x = v;
    #pragma unroll
    for (int o = 1; o < 32; o <<= 1) {
        int t = __shfl_up_sync(0xffffffffu, x, o);
        if (lane >= o) x += t;
    }
    if (lane == 31) wsum[wid] = x;
    __syncthreads();
    if (wid == 0) {
        int w = wsum[lane];
        #pragma unroll
        for (int o = 1; o < 32; o <<= 1) {
            int t = __shfl_up_sync(0xffffffffu, w, o);
            if (lane >= o) w += t;
        }
        wsum[lane] = w;
    }
    __syncthreads();
    int wbase = wid ? wsum[wid - 1] : 0;
    if (i < NN) g_rowptr[i] = wbase + x - v;
    if (tid == 1023) g_bsum[blockIdx.x] = wbase + x;
}

__global__ void k_scan2() {
    __shared__ int w0;
    int tid = threadIdx.x;            // 0..63
    int lane = tid & 31, w = tid >> 5;
    int v = (tid < SCAN_B) ? g_bsum[tid] : 0;
    int x = v;
    #pragma unroll
    for (int o = 1; o < 32; o <<= 1) {
        int t = __shfl_up_sync(0xffffffffu, x, o);
        if (lane >= o) x += t;
    }
    if (w == 0 && lane == 31) w0 = x;
    __syncthreads();
    int base = w ? w0 : 0;
    if (tid < SCAN_B) g_boff[tid] = base + x - v;
    if (tid == SCAN_B - 1) g_rowptr[NN] = base + x;
}

__global__ void k_scan3() {
    int i = blockIdx.x * 1024 + threadIdx.x;
    if (i < NN) {
        int r = g_rowptr[i] + g_boff[blockIdx.x];
        g_rowptr[i] = r;
        g_cursor[i] = r;
    }
}

__global__ void k_fill(const int* __restrict__ src, const int* __restrict__ dst) {
    int e4 = blockIdx.x * blockDim.x + threadIdx.x;
    if (e4 * 4 >= EE) return;
    int4 d = ((const int4*)dst)[e4];
    int4 s = ((const int4*)src)[e4];
    int p0 = atomicAdd(&g_cursor[d.x], 1);
    int p1 = atomicAdd(&g_cursor[d.y], 1);
    int p2 = atomicAdd(&g_cursor[d.z], 1);
    int p3 = atomicAdd(&g_cursor[d.w], 1);
    g_esrc[p0] = s.x;
    g_esrc[p1] = s.y;
    g_esrc[p2] = s.z;
    g_esrc[p3] = s.w;
}

// ---------------- input GEMM (1xtf32): h = x0 = relu(x @ W_in + b_in) ------
__global__ void k_gemm_in(const float* __restrict__ x, const float* __restrict__ bias) {
    extern __shared__ float sm[];
    float* As = sm;                 // [128][36] raw fp32 activations
    float* Wh = sm + 128 * 36;      // [32][100]
    int tid = threadIdx.x;
    int warp = tid >> 5, lane = tid & 31;
    int wm = warp >> 1, wn = warp & 1;
    int g = lane >> 2, q = lane & 3;
    int row0 = blockIdx.x * 128;

    float c[2][6][4];
    #pragma unroll
    for (int mt = 0; mt < 2; mt++)
        #pragma unroll
        for (int nt = 0; nt < 6; nt++)
            #pragma unroll
            for (int i = 0; i < 4; i++) c[mt][nt][i] = 0.f;

    for (int kb = 0; kb < NF / 32; kb++) {
        #pragma unroll
        for (int t = 0; t < 4; t++) {
            int idx = tid + t * 256;
            int r = idx >> 3, c4 = idx & 7;
            float4 v = make_float4(0.f, 0.f, 0.f, 0.f);
            if (row0 + r < NN)
                v = ((const float4*)x)[(size_t)(row0 + r) * (NF / 4) + kb * 8 + c4];
            *(float4*)&As[r * 36 + c4 * 4] = v;
        }
        #pragma unroll
        for (int t = 0; t < 4; t++) {
            int i = tid + t * 256;
            if (i < 800) {
                int r = i / 25, cc = i % 25;
                *(float4*)&Wh[r * LDW + cc * 4] = *(const float4*)&g_Wih[(kb * 32 + r) * LDW + cc * 4];
            }
        }
        __syncthreads();

        #pragma unroll
        for (int ks = 0; ks < 4; ks++) {
            uint32_t a[2][4], b[6][2];
            #pragma unroll
            for (int mt = 0; mt < 2; mt++) {
                int rbase = wm * 32 + mt * 16 + g;
                #pragma unroll
                for (int ii = 0; ii < 4; ii++) {
                    int rr = rbase + (ii & 1) * 8;
                    int kk = ks * 8 + q + (ii >> 1) * 4;
                    a[mt][ii] = f2tf(As[rr * 36 + kk]);
                }
            }
            #pragma unroll
            for (int nt = 0; nt < 6; nt++) {
                int ncol = wn * 48 + nt * 8 + g;
                int k0 = ks * 8 + q;
                b[nt][0] = __float_as_uint(Wh[k0 * LDW + ncol]);
                b[nt][1] = __float_as_uint(Wh[(k0 + 4) * LDW + ncol]);
            }
            #pragma unroll
            for (int mt = 0; mt < 2; mt++)
                #pragma unroll
                for (int nt = 0; nt < 6; nt++)
                    mma8(c[mt][nt], a[mt], b[nt]);
        }
        __syncthreads();
    }

    #pragma unroll
    for (int mt = 0; mt < 2; mt++) {
        #pragma unroll
        for (int nt = 0; nt < 6; nt++) {
            int col = wn * 48 + nt * 8 + 2 * q;
            float b0 = bias[col], b1 = bias[col + 1];
            int r0 = row0 + wm * 32 + mt * 16 + g;
            if (r0 < NN) {
                float2 v;
                v.x = fmaxf(c[mt][nt][0] + b0, 0.f);
                v.y = fmaxf(c[mt][nt][1] + b1, 0.f);
                *(float2*)&g_h [r0 * NH + col] = v;
                *(float2*)&g_x0[r0 * NH + col] = v;
            }
            int r1 = r0 + 8;
            if (r1 < NN) {
                float2 v;
                v.x = fmaxf(c[mt][nt][2] + b0, 0.f);
                v.y = fmaxf(c[mt][nt][3] + b1, 0.f);
                *(float2*)&g_h [r1 * NH + col] = v;
                *(float2*)&g_x0[r1 * NH + col] = v;
            }
        }
    }
}

// ---------------- aggregation: hc = 0.9*segsum(h[src]->dst) + 0.1*x0 -------
__global__ void k_agg() {
    int gw = (blockIdx.x * 256 + threadIdx.x) >> 5;
    int lane = threadIdx.x & 31;
    if (gw >= NN) return;
    int s = g_rowptr[gw];
    int e = g_rowptr[gw + 1];
    if (lane >= 24) return;
    const float4* __restrict__ h4 = (const float4*)g_h;
    float4 acc = make_float4(0.f, 0.f, 0.f, 0.f);
    int i = s;
    for (; i + 8 <= e; i += 8) {
        int s0 = g_esrc[i],     s1 = g_esrc[i + 1];
        int s2 = g_esrc[i + 2], s3 = g_esrc[i + 3];
        int s4 = g_esrc[i + 4], s5 = g_esrc[i + 5];
        int s6 = g_esrc[i + 6], s7 = g_esrc[i + 7];
        float4 v0 = h4[s0 * 24 + lane];
        float4 v1 = h4[s1 * 24 + lane];
        float4 v2 = h4[s2 * 24 + lane];
        float4 v3 = h4[s3 * 24 + lane];
        float4 v4 = h4[s4 * 24 + lane];
        float4 v5 = h4[s5 * 24 + lane];
        float4 v6 = h4[s6 * 24 + lane];
        float4 v7 = h4[s7 * 24 + lane];
        acc.x += ((v0.x + v1.x) + (v2.x + v3.x)) + ((v4.x + v5.x) + (v6.x + v7.x));
        acc.y += ((v0.y + v1.y) + (v2.y + v3.y)) + ((v4.y + v5.y) + (v6.y + v7.y));
        acc.z += ((v0.z + v1.z) + (v2.z + v3.z)) + ((v4.z + v5.z) + (v6.z + v7.z));
        acc.w += ((v0.w + v1.w) + (v2.w + v3.w)) + ((v4.w + v5.w) + (v6.w + v7.w));
    }
    for (; i < e; i++) {
        float4 v = h4[g_esrc[i] * 24 + lane];
        acc.x += v.x; acc.y += v.y; acc.z += v.z; acc.w += v.w;
    }
    float4 x0v = ((const float4*)g_x0)[gw * 24 + lane];
    float4 hc;
    const float OA = 1.0f - ALPHA;
    hc.x = OA * acc.x + ALPHA * x0v.x;
    hc.y = OA * acc.y + ALPHA * x0v.y;
    hc.z = OA * acc.z + ALPHA * x0v.z;
    hc.w = OA * acc.w + ALPHA * x0v.w;
    ((float4*)g_hc)[gw * 24 + lane] = hc;
}

// ---------------- persistent layer GEMM (1xtf32 on beta term) --------------
// h = relu((1-b)*hc + b*(hc @ W)); W loaded once per CTA, loop over tiles
__global__ void k_layer(int l, float beta) {
    extern __shared__ float sm[];
    float* As = sm;                 // [128][100] raw fp32 hc
    float* Ws = sm + 128 * LDW;     // [96][100] tf32-valid W
    int tid = threadIdx.x;
    int warp = tid >> 5, lane = tid & 31;
    int wm = warp >> 1, wn = warp & 1;
    int g = lane >> 2, q = lane & 3;

    // load W once
    const float* Wg = g_Wm + (size_t)l * NH * LDW;
    #pragma unroll
    for (int t = 0; t < 10; t++) {
        int i = tid + t * 256;
        if (i < 2400) {
            int r = i / 25, cc = i % 25;
            *(float4*)&Ws[r * LDW + cc * 4] = *(const float4*)&Wg[r * LDW + cc * 4];
        }
    }

    float ob = 1.f - beta;
    for (int tile = blockIdx.x; tile < GBLK128; tile += gridDim.x) {
        int row0 = tile * 128;
        __syncthreads();   // previous iteration's As readers done (also covers Ws 1st iter)
        #pragma unroll
        for (int t = 0; t < 12; t++) {
            int i = tid + t * 256;
            int r = i / 24, cc = i % 24;
            float4 v = make_float4(0.f, 0.f, 0.f, 0.f);
            if (row0 + r < NN) v = ((const float4*)g_hc)[(row0 + r) * 24 + cc];
            *(float4*)&As[r * LDW + cc * 4] = v;
        }
        __syncthreads();

        float c[2][6][4];
        #pragma unroll
        for (int mt = 0; mt < 2; mt++)
            #pragma unroll
            for (int nt = 0; nt < 6; nt++)
                #pragma unroll
                for (int i = 0; i < 4; i++) c[mt][nt][i] = 0.f;

        #pragma unroll
        for (int ks = 0; ks < NH / 8; ks++) {
            uint32_t a[2][4], b[6][2];
            #pragma unroll
            for (int mt = 0; mt < 2; mt++) {
                int rbase = wm * 32 + mt * 16 + g;
                #pragma unroll
                for (int ii = 0; ii < 4; ii++) {
                    int rr = rbase + (ii & 1) * 8;
                    int kk = ks * 8 + q + (ii >> 1) * 4;
                    a[mt][ii] = f2tf(As[rr * LDW + kk]);
                }
            }
            #pragma unroll
            for (int nt = 0; nt < 6; nt++) {
                int ncol = wn * 48 + nt * 8 + g;
                int k0 = ks * 8 + q;
                b[nt][0] = __float_as_uint(Ws[k0 * LDW + ncol]);
                b[nt][1] = __float_as_uint(Ws[(k0 + 4) * LDW + ncol]);
            }
            #pragma unroll
            for (int mt = 0; mt < 2; mt++)
                #pragma unroll
                for (int nt = 0; nt < 6; nt++)
                    mma8(c[mt][nt], a[mt], b[nt]);
        }

        #pragma unroll
        for (int mt = 0; mt < 2; mt++) {
            #pragma unroll
            for (int nt = 0; nt < 6; nt++) {
                int col = wn * 48 + nt * 8 + 2 * q;
                int rl0 = wm * 32 + mt * 16 + g;
                int r0 = row0 + rl0;
                if (r0 < NN) {
                    float hc0 = As[rl0 * LDW + col];
                    float hc1 = As[rl0 * LDW + col + 1];
                    float2 v;
                    v.x = fmaxf(ob * hc0 + beta * c[mt][nt][0], 0.f);
                    v.y = fmaxf(ob * hc1 + beta * c[mt][nt][1], 0.f);
                    *(float2*)&g_h[r0 * NH + col] = v;
                }
                int rl1 = rl0 + 8;
                int r1 = r0 + 8;
                if (r1 < NN) {
                    float hc0 = As[rl1 * LDW + col];
                    float hc1 = As[rl1 * LDW + col + 1];
                    float2 v;
                    v.x = fmaxf(ob * hc0 + beta * c[mt][nt][2], 0.f);
                    v.y = fmaxf(ob * hc1 + beta * c[mt][nt][3], 0.f);
                    *(float2*)&g_h[r1 * NH + col] = v;
                }
            }
        }
    }
}

// ---------------- output GEMM (1xtf32) + log-softmax -----------------------
// M=128 tile, 8 warps (4Mx2N), warp tile 32x32. Logits staged in smem.
__global__ void k_out(const float* __restrict__ bias, float* __restrict__ out) {
    extern __shared__ float sm[];
    float* As = sm;                 // [128][100] h tile (fp32); later logits [128][68]
    float* Ws = sm + 128 * LDW;     // [96][72] tf32 W_out
    float* Lg = sm;                 // logits alias (As region, 128*68 <= 128*100)
    int tid = threadIdx.x;
    int warp = tid >> 5, lane = tid & 31;
    int wm = warp >> 1, wn = warp & 1;
    int g = lane >> 2, q = lane & 3;
    int row0 = blockIdx.x * 128;

    #pragma unroll
    for (int t = 0; t < 7; t++) {
        int i = tid + t * 256;
        if (i < NH * LDO / 4) {
            ((float4*)Ws)[i] = ((const float4*)g_Wo)[i];
        }
    }
    #pragma unroll
    for (int t = 0; t < 12; t++) {
        int i = tid + t * 256;
        int r = i / 24, cc = i % 24;
        float4 v = make_float4(0.f, 0.f, 0.f, 0.f);
        if (row0 + r < NN) v = ((const float4*)g_h)[(row0 + r) * 24 + cc];
        *(float4*)&As[r * LDW + cc * 4] = v;
    }
    __syncthreads();

    float c[2][4][4];
    #pragma unroll
    for (int mt = 0; mt < 2; mt++)
        #pragma unroll
        for (int nt = 0; nt < 4; nt++)
            #pragma unroll
            for (int i = 0; i < 4; i++) c[mt][nt][i] = 0.f;

    #pragma unroll
    for (int ks = 0; ks < NH / 8; ks++) {
        uint32_t a[2][4], b[4][2];
        #pragma unroll
        for (int mt = 0; mt < 2; mt++) {
            int rbase = wm * 32 + mt * 16 + g;
            #pragma unroll
            for (int ii = 0; ii < 4; ii++) {
                int rr = rbase + (ii & 1) * 8;
                int kk = ks * 8 + q + (ii >> 1) * 4;
                a[mt][ii] = f2tf(As[rr * LDW + kk]);
            }
        }
        #pragma unroll
        for (int nt = 0; nt < 4; nt++) {
            int ncol = wn * 32 + nt * 8 + g;
            int k0 = ks * 8 + q;
            b[nt][0] = __float_as_uint(Ws[k0 * LDO + ncol]);
            b[nt][1] = __float_as_uint(Ws[(k0 + 4) * LDO + ncol]);
        }
        #pragma unroll
        for (int mt = 0; mt < 2; mt++)
            #pragma unroll
            for (int nt = 0; nt < 4; nt++)
                mma8(c[mt][nt], a[mt], b[nt]);
    }
    __syncthreads();   // done reading As; reuse as logits

    // stage logits (+bias) into smem
    #pragma unroll
    for (int mt = 0; mt < 2; mt++) {
        #pragma unroll
        for (int nt = 0; nt < 4; nt++) {
            int col = wn * 32 + nt * 8 + 2 * q;
            float b0 = bias[col], b1 = bias[col + 1];
            int rl0 = wm * 32 + mt * 16 + g;
            float2 v0;
            v0.x = c[mt][nt][0] + b0;
            v0.y = c[mt][nt][1] + b1;
            *(float2*)&Lg[rl0 * LDL + col] = v0;
            int rl1 = rl0 + 8;
            float2 v1;
            v1.x = c[mt][nt][2] + b0;
            v1.y = c[mt][nt][3] + b1;
            *(float2*)&Lg[rl1 * LDL + col] = v1;
        }
    }
    __syncthreads();

    // softmax: thread pair (tid, tid^1) handles one row (halves of 32 cols)
    {
        int row = tid >> 1;
        int half = tid & 1;
        float vals[32];
        #pragma unroll
        for (int j4 = 0; j4 < 8; j4++) {
            float4 v = *(float4*)&Lg[row * LDL + half * 32 + j4 * 4];
            vals[j4 * 4 + 0] = v.x;
            vals[j4 * 4 + 1] = v.y;
            vals[j4 * 4 + 2] = v.z;
            vals[j4 * 4 + 3] = v.w;
        }
        float m = vals[0];
        #pragma unroll
        for (int j = 1; j < 32; j++) m = fmaxf(m, vals[j]);
        m = fmaxf(m, __shfl_xor_sync(0xffffffffu, m, 1));
        float s = 0.f;
        #pragma unroll
        for (int j = 0; j < 32; j++) s += __expf(vals[j] - m);
        s += __shfl_xor_sync(0xffffffffu, s, 1);
        float lse = m + logf(s);
        int grow = row0 + row;
        if (grow < NN) {
            #pragma unroll
            for (int j4 = 0; j4 < 8; j4++) {
                float4 v;
                v.x = vals[j4 * 4 + 0] - lse;
                v.y = vals[j4 * 4 + 1] - lse;
                v.z = vals[j4 * 4 + 2] - lse;
                v.w = vals[j4 * 4 + 3] - lse;
                *(float4*)&out[grow * NC + half * 32 + j4 * 4] = v;
            }
        }
    }
}

// ---------------- launch ----------------------------------------------------
extern "C" void kernel_launch(void* const* d_in, const int* in_sizes, int n_in,
                              void* d_out, int out_size) {
    const float* x      = (const float*)d_in[0];
    const int*   ei     = (const int*)  d_in[1];
    const float* W_in   = (const float*)d_in[2];
    const float* b_in   = (const float*)d_in[3];
    const float* conv_W = (const float*)d_in[4];
    const float* W_out  = (const float*)d_in[5];
    const float* b_out  = (const float*)d_in[6];
    float* out = (float*)d_out;

    const int* src = ei;        // edge_index[0]
    const int* dst = ei + EE;   // edge_index[1]

    const int IN_SMEM    = (128 * 36 + 32 * LDW) * 4;       // 31232
    const int LAYER_SMEM = (128 * LDW + NH * LDW) * 4;      // 89600
    const int OUT_SMEM   = (128 * LDW + NH * LDO) * 4;      // 78848
    cudaFuncSetAttribute(k_gemm_in, cudaFuncAttributeMaxDynamicSharedMemorySize, IN_SMEM);
    cudaFuncSetAttribute(k_layer,   cudaFuncAttributeMaxDynamicSharedMemorySize, LAYER_SMEM);
    cudaFuncSetAttribute(k_out,     cudaFuncAttributeMaxDynamicSharedMemorySize, OUT_SMEM);

    // weight prep (tf32 rounding); k_prep_in also zeroes g_deg
    k_prep_in<<<(NF * LDW + 255) / 256, 256>>>(W_in);
    k_prep_wm<<<(NL * NH * LDW + 255) / 256, 256>>>(conv_W);
    k_prep_out<<<(NH * LDO + 255) / 256, 256>>>(W_out);

    // CSR build (multi-block scan)
    k_hist<<<(EE / 4 + 255) / 256, 256>>>(dst);
    k_scan1<<<SCAN_B, 1024>>>();
    k_scan2<<<1, 64>>>();
    k_scan3<<<SCAN_B, 1024>>>();
    k_fill<<<(EE / 4 + 255) / 256, 256>>>(src, dst);

    // input projection -> g_h (+ g_x0)
    k_gemm_in<<<GBLK128, 256, IN_SMEM>>>(x, b_in);

    // 8 GCNII layers (split agg + persistent layer GEMM)
    for (int l = 0; l < NL; l++) {
        float beta = (float)log(0.5 / (double)(l + 1) + 1.0);
        k_agg<<<NN / 8, 256>>>();
        k_layer<<<PERS, 256, LAYER_SMEM>>>(l, beta);
    }

    // output + log-softmax
    k_out<<<GBLK128, 256, OUT_SMEM>>>(b_out, out);
}

// round 9
// speedup vs baseline: 1.7730x; 1.0010x over previous
#include <cuda_runtime.h>
#include <cuda_fp16.h>
#include <math.h>
#include <stdint.h>

constexpr int NN = 50000;   // nodes
constexpr int EE = 800000;  // edges
constexpr int NF = 512;     // input features
constexpr int NH = 96;      // hidden
constexpr int NC = 64;      // classes
constexpr int NL = 8;       // layers
constexpr float ALPHA = 0.1f;
constexpr int LDW = 100;    // padded leading dim (bank-conflict-free fragments)
constexpr int LDO = 72;     // padded leading dim for W_out
constexpr int LDL = 68;     // padded leading dim for logits tile

constexpr int GBLK128 = (NN + 127) / 128;   // 391
constexpr int SCAN_B  = (NN + 1023) / 1024; // 49 scan blocks
constexpr int PERS    = 296;                // persistent CTAs for k_layer

// ---------------- scratch (device globals; no allocations allowed) ----------
__device__ __align__(16) float  g_h [NN * NH];
__device__ __align__(16) __half g_hf[NN * NH];   // fp16 shadow of h * 16^-l
__device__ __align__(16) float  g_x0[NN * NH];
__device__ __align__(16) float  g_hc[NN * NH];
__device__ int g_deg[NN];
__device__ int g_rowptr[NN + 1];
__device__ int g_cursor[NN];
__device__ int g_esrc[EE];
__device__ int g_bsum[SCAN_B];
__device__ int g_boff[SCAN_B];
// pre-converted weights (tf32-valid fp32 bit patterns), padded
__device__ __align__(16) float g_Wih[NF * LDW];
__device__ __align__(16) float g_Wm [NL * NH * LDW];
__device__ __align__(16) float g_Wo [NH * LDO];

// ---------------- tf32 helpers ----------------
__device__ __forceinline__ uint32_t f2tf(float f) {
    uint32_t u;
    asm("cvt.rna.tf32.f32 %0, %1;" : "=r"(u) : "f"(f));
    return u;
}

__device__ __forceinline__ void mma8(float* c, const uint32_t* a, const uint32_t* b) {
    asm volatile(
        "mma.sync.aligned.m16n8k8.row.col.f32.tf32.tf32.f32 "
        "{%0,%1,%2,%3}, {%4,%5,%6,%7}, {%8,%9}, {%0,%1,%2,%3};"
        : "+f"(c[0]), "+f"(c[1]), "+f"(c[2]), "+f"(c[3])
        : "r"(a[0]), "r"(a[1]), "r"(a[2]), "r"(a[3]), "r"(b[0]), "r"(b[1]));
}

// ---------------- weight prep (also zeroes g_deg) ----------------
__global__ void k_prep_in(const float* __restrict__ W) {
    int idx = blockIdx.x * blockDim.x + threadIdx.x;
    if (idx < NN) g_deg[idx] = 0;
    if (idx >= NF * LDW) return;
    int k = idx / LDW, n = idx % LDW;
    float hi = 0.f;
    if (n < NH) hi = __uint_as_float(f2tf(W[k * NH + n]));
    g_Wih[idx] = hi;
}

__global__ void k_prep_wm(const float* __restrict__ convW) {
    int idx = blockIdx.x * blockDim.x + threadIdx.x;
    if (idx >= NL * NH * LDW) return;
    int l = idx / (NH * LDW);
    int r = (idx / LDW) % NH;
    int n = idx % LDW;
    float v = 0.f;
    if (n < NH) v = __uint_as_float(f2tf(convW[l * NH * NH + r * NH + n]));
    g_Wm[idx] = v;
}

__global__ void k_prep_out(const float* __restrict__ Wout) {
    int idx = blockIdx.x * blockDim.x + threadIdx.x;
    if (idx >= NH * LDO) return;
    int r = idx / LDO, n = idx % LDO;
    float v = 0.f;
    if (n < NC) v = __uint_as_float(f2tf(Wout[r * NC + n]));
    g_Wo[idx] = v;
}

// ---------------- CSR build ----------------
__global__ void k_hist(const int* __restrict__ dst) {
    int e4 = blockIdx.x * blockDim.x + threadIdx.x;
    if (e4 * 4 >= EE) return;
    int4 d = ((const int4*)dst)[e4];
    atomicAdd(&g_deg[d.x], 1);
    atomicAdd(&g_deg[d.y], 1);
    atomicAdd(&g_deg[d.z], 1);
    atomicAdd(&g_deg[d.w], 1);
}

__global__ void k_scan1() {
    __shared__ int wsum[32];
    int tid = threadIdx.x, lane = tid & 31, wid = tid >> 5;
    int i = blockIdx.x * 1024 + tid;
    int v = (i < NN) ? g_deg[i] : 0;
    int x = v;
    #pragma unroll
    for (int o = 1; o < 32; o <<= 1) {
        int t = __shfl_up_sync(0xffffffffu, x, o);
        if (lane >= o) x += t;
    }
    if (lane == 31) wsum[wid] = x;
    __syncthreads();
    if (wid == 0) {
        int w = wsum[lane];
        #pragma unroll
        for (int o = 1; o < 32; o <<= 1) {
            int t = __shfl_up_sync(0xffffffffu, w, o);
            if (lane >= o) w += t;
        }
        wsum[lane] = w;
    }
    __syncthreads();
    int wbase = wid ? wsum[wid - 1] : 0;
    if (i < NN) g_rowptr[i] = wbase + x - v;
    if (tid == 1023) g_bsum[blockIdx.x] = wbase + x;
}

__global__ void k_scan2() {
    __shared__ int w0;
    int tid = threadIdx.x;            // 0..63
    int lane = tid & 31, w = tid >> 5;
    int v = (tid < SCAN_B) ? g_bsum[tid] : 0;
    int x = v;
    #pragma unroll
    for (int o = 1; o < 32; o <<= 1) {
        int t = __shfl_up_sync(0xffffffffu, x, o);
        if (lane >= o) x += t;
    }
    if (w == 0 && lane == 31) w0 = x;
    __syncthreads();
    int base = w ? w0 : 0;
    if (tid < SCAN_B) g_boff[tid] = base + x - v;
    if (tid == SCAN_B - 1) g_rowptr[NN] = base + x;
}

__global__ void k_scan3() {
    int i = blockIdx.x * 1024 + threadIdx.x;
    if (i < NN) {
        int r = g_rowptr[i] + g_boff[blockIdx.x];
        g_rowptr[i] = r;
        g_cursor[i] = r;
    }
}

__global__ void k_fill(const int* __restrict__ src, const int* __restrict__ dst) {
    int e4 = blockIdx.x * blockDim.x + threadIdx.x;
    if (e4 * 4 >= EE) return;
    int4 d = ((const int4*)dst)[e4];
    int4 s = ((const int4*)src)[e4];
    int p0 = atomicAdd(&g_cursor[d.x], 1);
    int p1 = atomicAdd(&g_cursor[d.y], 1);
    int p2 = atomicAdd(&g_cursor[d.z], 1);
    int p3 = atomicAdd(&g_cursor[d.w], 1);
    g_esrc[p0] = s.x;
    g_esrc[p1] = s.y;
    g_esrc[p2] = s.z;
    g_esrc[p3] = s.w;
}

// ---------------- input GEMM (1xtf32): h = x0 = relu(x @ W_in + b_in) ------
// fp16 shadow written with scale 1 (values O(1) at this stage)
__global__ void k_gemm_in(const float* __restrict__ x, const float* __restrict__ bias) {
    extern __shared__ float sm[];
    float* As = sm;                 // [128][36] raw fp32 activations
    float* Wh = sm + 128 * 36;      // [32][100]
    int tid = threadIdx.x;
    int warp = tid >> 5, lane = tid & 31;
    int wm = warp >> 1, wn = warp & 1;
    int g = lane >> 2, q = lane & 3;
    int row0 = blockIdx.x * 128;

    float c[2][6][4];
    #pragma unroll
    for (int mt = 0; mt < 2; mt++)
        #pragma unroll
        for (int nt = 0; nt < 6; nt++)
            #pragma unroll
            for (int i = 0; i < 4; i++) c[mt][nt][i] = 0.f;

    for (int kb = 0; kb < NF / 32; kb++) {
        #pragma unroll
        for (int t = 0; t < 4; t++) {
            int idx = tid + t * 256;
            int r = idx >> 3, c4 = idx & 7;
            float4 v = make_float4(0.f, 0.f, 0.f, 0.f);
            if (row0 + r < NN)
                v = ((const float4*)x)[(size_t)(row0 + r) * (NF / 4) + kb * 8 + c4];
            *(float4*)&As[r * 36 + c4 * 4] = v;
        }
        #pragma unroll
        for (int t = 0; t < 4; t++) {
            int i = tid + t * 256;
            if (i < 800) {
                int r = i / 25, cc = i % 25;
                *(float4*)&Wh[r * LDW + cc * 4] = *(const float4*)&g_Wih[(kb * 32 + r) * LDW + cc * 4];
            }
        }
        __syncthreads();

        #pragma unroll
        for (int ks = 0; ks < 4; ks++) {
            uint32_t a[2][4], b[6][2];
            #pragma unroll
            for (int mt = 0; mt < 2; mt++) {
                int rbase = wm * 32 + mt * 16 + g;
                #pragma unroll
                for (int ii = 0; ii < 4; ii++) {
                    int rr = rbase + (ii & 1) * 8;
                    int kk = ks * 8 + q + (ii >> 1) * 4;
                    a[mt][ii] = f2tf(As[rr * 36 + kk]);
                }
            }
            #pragma unroll
            for (int nt = 0; nt < 6; nt++) {
                int ncol = wn * 48 + nt * 8 + g;
                int k0 = ks * 8 + q;
                b[nt][0] = __float_as_uint(Wh[k0 * LDW + ncol]);
                b[nt][1] = __float_as_uint(Wh[(k0 + 4) * LDW + ncol]);
            }
            #pragma unroll
            for (int mt = 0; mt < 2; mt++)
                #pragma unroll
                for (int nt = 0; nt < 6; nt++)
                    mma8(c[mt][nt], a[mt], b[nt]);
        }
        __syncthreads();
    }

    #pragma unroll
    for (int mt = 0; mt < 2; mt++) {
        #pragma unroll
        for (int nt = 0; nt < 6; nt++) {
            int col = wn * 48 + nt * 8 + 2 * q;
            float b0 = bias[col], b1 = bias[col + 1];
            int r0 = row0 + wm * 32 + mt * 16 + g;
            if (r0 < NN) {
                float2 v;
                v.x = fmaxf(c[mt][nt][0] + b0, 0.f);
                v.y = fmaxf(c[mt][nt][1] + b1, 0.f);
                *(float2*)&g_h [r0 * NH + col] = v;
                *(float2*)&g_x0[r0 * NH + col] = v;
                *(__half2*)&g_hf[r0 * NH + col] = __floats2half2_rn(v.x, v.y);
            }
            int r1 = r0 + 8;
            if (r1 < NN) {
                float2 v;
                v.x = fmaxf(c[mt][nt][2] + b0, 0.f);
                v.y = fmaxf(c[mt][nt][3] + b1, 0.f);
                *(float2*)&g_h [r1 * NH + col] = v;
                *(float2*)&g_x0[r1 * NH + col] = v;
                *(__half2*)&g_hf[r1 * NH + col] = __floats2half2_rn(v.x, v.y);
            }
        }
    }
}

// ---------------- aggregation (scaled fp16 gather, fp32 accumulate) --------
// shadow holds h * S_l (S_l = 16^-l); hc = (0.9/S_l)*segsum(hf) + 0.1*x0
// one warp per node; lanes 0..23 each own a uint2 (4 fp16 features)
__global__ void k_agg(float oa_unscale /* = 0.9 * 16^l */) {
    int gw = (blockIdx.x * 256 + threadIdx.x) >> 5;
    int lane = threadIdx.x & 31;
    if (gw >= NN) return;
    int s = g_rowptr[gw];
    int e = g_rowptr[gw + 1];
    if (lane >= 24) return;
    const uint2* __restrict__ hf = (const uint2*)g_hf;
    float4 acc = make_float4(0.f, 0.f, 0.f, 0.f);
    int i = s;
    for (; i + 8 <= e; i += 8) {
        int s0 = g_esrc[i],     s1 = g_esrc[i + 1];
        int s2 = g_esrc[i + 2], s3 = g_esrc[i + 3];
        int s4 = g_esrc[i + 4], s5 = g_esrc[i + 5];
        int s6 = g_esrc[i + 6], s7 = g_esrc[i + 7];
        uint2 u0 = hf[s0 * 24 + lane];
        uint2 u1 = hf[s1 * 24 + lane];
        uint2 u2 = hf[s2 * 24 + lane];
        uint2 u3 = hf[s3 * 24 + lane];
        uint2 u4 = hf[s4 * 24 + lane];
        uint2 u5 = hf[s5 * 24 + lane];
        uint2 u6 = hf[s6 * 24 + lane];
        uint2 u7 = hf[s7 * 24 + lane];
        #pragma unroll
        for (int k = 0; k < 8; k++) {
            uint2 u = (k == 0) ? u0 : (k == 1) ? u1 : (k == 2) ? u2 : (k == 3) ? u3
                   : (k == 4) ? u4 : (k == 5) ? u5 : (k == 6) ? u6 : u7;
            float2 fa = __half22float2(*reinterpret_cast<const __half2*>(&u.x));
            float2 fb = __half22float2(*reinterpret_cast<const __half2*>(&u.y));
            acc.x += fa.x; acc.y += fa.y; acc.z += fb.x; acc.w += fb.y;
        }
    }
    for (; i < e; i++) {
        uint2 u = hf[g_esrc[i] * 24 + lane];
        float2 fa = __half22float2(*reinterpret_cast<const __half2*>(&u.x));
        float2 fb = __half22float2(*reinterpret_cast<const __half2*>(&u.y));
        acc.x += fa.x; acc.y += fa.y; acc.z += fb.x; acc.w += fb.y;
    }
    float4 x0v = ((const float4*)g_x0)[gw * 24 + lane];
    float4 hc;
    hc.x = oa_unscale * acc.x + ALPHA * x0v.x;
    hc.y = oa_unscale * acc.y + ALPHA * x0v.y;
    hc.z = oa_unscale * acc.z + ALPHA * x0v.z;
    hc.w = oa_unscale * acc.w + ALPHA * x0v.w;
    ((float4*)g_hc)[gw * 24 + lane] = hc;
}

// ---------------- persistent layer GEMM (1xtf32 on beta term) --------------
// h = relu((1-b)*hc + b*(hc @ W)); fp16 shadow written as h * sc_out
__global__ void k_layer(int l, float beta, float sc_out) {
    extern __shared__ float sm[];
    float* As = sm;                 // [128][100] raw fp32 hc
    float* Ws = sm + 128 * LDW;     // [96][100] tf32-valid W
    int tid = threadIdx.x;
    int warp = tid >> 5, lane = tid & 31;
    int wm = warp >> 1, wn = warp & 1;
    int g = lane >> 2, q = lane & 3;

    // load W once
    const float* Wg = g_Wm + (size_t)l * NH * LDW;
    #pragma unroll
    for (int t = 0; t < 10; t++) {
        int i = tid + t * 256;
        if (i < 2400) {
            int r = i / 25, cc = i % 25;
            *(float4*)&Ws[r * LDW + cc * 4] = *(const float4*)&Wg[r * LDW + cc * 4];
        }
    }

    float ob = 1.f - beta;
    for (int tile = blockIdx.x; tile < GBLK128; tile += gridDim.x) {
        int row0 = tile * 128;
        __syncthreads();   // previous iteration's As readers done (covers Ws 1st iter)
        #pragma unroll
        for (int t = 0; t < 12; t++) {
            int i = tid + t * 256;
            int r = i / 24, cc = i % 24;
            float4 v = make_float4(0.f, 0.f, 0.f, 0.f);
            if (row0 + r < NN) v = ((const float4*)g_hc)[(row0 + r) * 24 + cc];
            *(float4*)&As[r * LDW + cc * 4] = v;
        }
        __syncthreads();

        float c[2][6][4];
        #pragma unroll
        for (int mt = 0; mt < 2; mt++)
            #pragma unroll
            for (int nt = 0; nt < 6; nt++)
                #pragma unroll
                for (int i = 0; i < 4; i++) c[mt][nt][i] = 0.f;

        #pragma unroll
        for (int ks = 0; ks < NH / 8; ks++) {
            uint32_t a[2][4], b[6][2];
            #pragma unroll
            for (int mt = 0; mt < 2; mt++) {
                int rbase = wm * 32 + mt * 16 + g;
                #pragma unroll
                for (int ii = 0; ii < 4; ii++) {
                    int rr = rbase + (ii & 1) * 8;
                    int kk = ks * 8 + q + (ii >> 1) * 4;
                    a[mt][ii] = f2tf(As[rr * LDW + kk]);
                }
            }
            #pragma unroll
            for (int nt = 0; nt < 6; nt++) {
                int ncol = wn * 48 + nt * 8 + g;
                int k0 = ks * 8 + q;
                b[nt][0] = __float_as_uint(Ws[k0 * LDW + ncol]);
                b[nt][1] = __float_as_uint(Ws[(k0 + 4) * LDW + ncol]);
            }
            #pragma unroll
            for (int mt = 0; mt < 2; mt++)
                #pragma unroll
                for (int nt = 0; nt < 6; nt++)
                    mma8(c[mt][nt], a[mt], b[nt]);
        }

        #pragma unroll
        for (int mt = 0; mt < 2; mt++) {
            #pragma unroll
            for (int nt = 0; nt < 6; nt++) {
                int col = wn * 48 + nt * 8 + 2 * q;
                int rl0 = wm * 32 + mt * 16 + g;
                int r0 = row0 + rl0;
                if (r0 < NN) {
                    float hc0 = As[rl0 * LDW + col];
                    float hc1 = As[rl0 * LDW + col + 1];
                    float2 v;
                    v.x = fmaxf(ob * hc0 + beta * c[mt][nt][0], 0.f);
                    v.y = fmaxf(ob * hc1 + beta * c[mt][nt][1], 0.f);
                    *(float2*)&g_h[r0 * NH + col] = v;
                    *(__half2*)&g_hf[r0 * NH + col] = __floats2half2_rn(v.x * sc_out, v.y * sc_out);
                }
                int rl1 = rl0 + 8;
                int r1 = r0 + 8;
                if (r1 < NN) {
                    float hc0 = As[rl1 * LDW + col];
                    float hc1 = As[rl1 * LDW + col + 1];
                    float2 v;
                    v.x = fmaxf(ob * hc0 + beta * c[mt][nt][2], 0.f);
                    v.y = fmaxf(ob * hc1 + beta * c[mt][nt][3], 0.f);
                    *(float2*)&g_h[r1 * NH + col] = v;
                    *(__half2*)&g_hf[r1 * NH + col] = __floats2half2_rn(v.x * sc_out, v.y * sc_out);
                }
            }
        }
    }
}

// ---------------- output GEMM (1xtf32) + log-softmax -----------------------
__global__ void k_out(const float* __restrict__ bias, float* __restrict__ out) {
    extern __shared__ float sm[];
    float* As = sm;                 // [128][100] h tile (fp32); later logits [128][68]
    float* Ws = sm + 128 * LDW;     // [96][72] tf32 W_out
    float* Lg = sm;                 // logits alias
    int tid = threadIdx.x;
    int warp = tid >> 5, lane = tid & 31;
    int wm = warp >> 1, wn = warp & 1;
    int g = lane >> 2, q = lane & 3;
    int row0 = blockIdx.x * 128;

    #pragma unroll
    for (int t = 0; t < 7; t++) {
        int i = tid + t * 256;
        if (i < NH * LDO / 4) {
            ((float4*)Ws)[i] = ((const float4*)g_Wo)[i];
        }
    }
    #pragma unroll
    for (int t = 0; t < 12; t++) {
        int i = tid + t * 256;
        int r = i / 24, cc = i % 24;
        float4 v = make_float4(0.f, 0.f, 0.f, 0.f);
        if (row0 + r < NN) v = ((const float4*)g_h)[(row0 + r) * 24 + cc];
        *(float4*)&As[r * LDW + cc * 4] = v;
    }
    __syncthreads();

    float c[2][4][4];
    #pragma unroll
    for (int mt = 0; mt < 2; mt++)
        #pragma unroll
        for (int nt = 0; nt < 4; nt++)
            #pragma unroll
            for (int i = 0; i < 4; i++) c[mt][nt][i] = 0.f;

    #pragma unroll
    for (int ks = 0; ks < NH / 8; ks++) {
        uint32_t a[2][4], b[4][2];
        #pragma unroll
        for (int mt = 0; mt < 2; mt++) {
            int rbase = wm * 32 + mt * 16 + g;
            #pragma unroll
            for (int ii = 0; ii < 4; ii++) {
                int rr = rbase + (ii & 1) * 8;
                int kk = ks * 8 + q + (ii >> 1) * 4;
                a[mt][ii] = f2tf(As[rr * LDW + kk]);
            }
        }
        #pragma unroll
        for (int nt = 0; nt < 4; nt++) {
            int ncol = wn * 32 + nt * 8 + g;
            int k0 = ks * 8 + q;
            b[nt][0] = __float_as_uint(Ws[k0 * LDO + ncol]);
            b[nt][1] = __float_as_uint(Ws[(k0 + 4) * LDO + ncol]);
        }
        #pragma unroll
        for (int mt = 0; mt < 2; mt++)
            #pragma unroll
            for (int nt = 0; nt < 4; nt++)
                mma8(c[mt][nt], a[mt], b[nt]);
    }
    __syncthreads();   // done reading As; reuse as logits

    #pragma unroll
    for (int mt = 0; mt < 2; mt++) {
        #pragma unroll
        for (int nt = 0; nt < 4; nt++) {
            int col = wn * 32 + nt * 8 + 2 * q;
            float b0 = bias[col], b1 = bias[col + 1];
            int rl0 = wm * 32 + mt * 16 + g;
            float2 v0;
            v0.x = c[mt][nt][0] + b0;
            v0.y = c[mt][nt][1] + b1;
            *(float2*)&Lg[rl0 * LDL + col] = v0;
            int rl1 = rl0 + 8;
            float2 v1;
            v1.x = c[mt][nt][2] + b0;
            v1.y = c[mt][nt][3] + b1;
            *(float2*)&Lg[rl1 * LDL + col] = v1;
        }
    }
    __syncthreads();

    {
        int row = tid >> 1;
        int half = tid & 1;
        float vals[32];
        #pragma unroll
        for (int j4 = 0; j4 < 8; j4++) {
            float4 v = *(float4*)&Lg[row * LDL + half * 32 + j4 * 4];
            vals[j4 * 4 + 0] = v.x;
            vals[j4 * 4 + 1] = v.y;
            vals[j4 * 4 + 2] = v.z;
            vals[j4 * 4 + 3] = v.w;
        }
        float m = vals[0];
        #pragma unroll
        for (int j = 1; j < 32; j++) m = fmaxf(m, vals[j]);
        m = fmaxf(m, __shfl_xor_sync(0xffffffffu, m, 1));
        float s = 0.f;
        #pragma unroll
        for (int j = 0; j < 32; j++) s += __expf(vals[j] - m);
        s += __shfl_xor_sync(0xffffffffu, s, 1);
        float lse = m + logf(s);
        int grow = row0 + row;
        if (grow < NN) {
            #pragma unroll
            for (int j4 = 0; j4 < 8; j4++) {
                float4 v;
                v.x = vals[j4 * 4 + 0] - lse;
                v.y = vals[j4 * 4 + 1] - lse;
                v.z = vals[j4 * 4 + 2] - lse;
                v.w = vals[j4 * 4 + 3] - lse;
                *(float4*)&out[grow * NC + half * 32 + j4 * 4] = v;
            }
        }
    }
}

// ---------------- launch ----------------------------------------------------
extern "C" void kernel_launch(void* const* d_in, const int* in_sizes, int n_in,
                              void* d_out, int out_size) {
    const float* x      = (const float*)d_in[0];
    const int*   ei     = (const int*)  d_in[1];
    const float* W_in   = (const float*)d_in[2];
    const float* b_in   = (const float*)d_in[3];
    const float* conv_W = (const float*)d_in[4];
    const float* W_out  = (const float*)d_in[5];
    const float* b_out  = (const float*)d_in[6];
    float* out = (float*)d_out;

    const int* src = ei;        // edge_index[0]
    const int* dst = ei + EE;   // edge_index[1]

    const int IN_SMEM    = (128 * 36 + 32 * LDW) * 4;       // 31232
    const int LAYER_SMEM = (128 * LDW + NH * LDW) * 4;      // 89600
    const int OUT_SMEM   = (128 * LDW + NH * LDO) * 4;      // 78848
    cudaFuncSetAttribute(k_gemm_in, cudaFuncAttributeMaxDynamicSharedMemorySize, IN_SMEM);
    cudaFuncSetAttribute(k_layer,   cudaFuncAttributeMaxDynamicSharedMemorySize, LAYER_SMEM);
    cudaFuncSetAttribute(k_out,     cudaFuncAttributeMaxDynamicSharedMemorySize, OUT_SMEM);

    // weight prep (tf32 rounding); k_prep_in also zeroes g_deg
    k_prep_in<<<(NF * LDW + 255) / 256, 256>>>(W_in);
    k_prep_wm<<<(NL * NH * LDW + 255) / 256, 256>>>(conv_W);
    k_prep_out<<<(NH * LDO + 255) / 256, 256>>>(W_out);

    // CSR build (multi-block scan)
    k_hist<<<(EE / 4 + 255) / 256, 256>>>(dst);
    k_scan1<<<SCAN_B, 1024>>>();
    k_scan2<<<1, 64>>>();
    k_scan3<<<SCAN_B, 1024>>>();
    k_fill<<<(EE / 4 + 255) / 256, 256>>>(src, dst);

    // input projection -> g_h (+ g_x0, fp16 shadow at scale 16^0 = 1)
    k_gemm_in<<<GBLK128, 256, IN_SMEM>>>(x, b_in);

    // 8 GCNII layers; fp16 shadow of stage l carries scale 16^-l
    for (int l = 0; l < NL; l++) {
        float beta = (float)log(0.5 / (double)(l + 1) + 1.0);
        float oa_unscale = 0.9f * ldexpf(1.f, 4 * l);      // 0.9 * 16^l  (exact pow2 factor)
        float sc_out     = ldexpf(1.f, -4 * (l + 1));      // 16^-(l+1)
        k_agg<<<NN / 8, 256>>>(oa_unscale);
        k_layer<<<PERS, 256, LAYER_SMEM>>>(l, beta, sc_out);
    }

    // output + log-softmax
    k_out<<<GBLK128, 256, OUT_SMEM>>>(b_out, out);
}